// round 7
// baseline (speedup 1.0000x reference)
#include <cuda_runtime.h>
#include <cuda_bf16.h>

// TextureMartingaleModule: per-channel 3x3 GLCM features, zero padding.
// x: [8,16,256,256] f32 -> out: [8,64,256,256] f32
//   contrast    = mean(((p-mean)/std)^2),  std = sqrt(sd/8)+eps
//   energy      = mean(p^2)
//   entropy     = -mean(p*log(p+eps))
//   homogeneity = 1 / mean(1 + |p-mean|)
// M = (f + eps) * e^{-0.5}   (theta = 1)
//
// Key identities exploited:
//   sd = S2 - S1*mean                      (no per-element dev pass for variance)
//   contrast = (8/9) / (1 + eps*rsqrt(sd/8))^2 ~= (8/9)*(1 - 2*eps*rsqrt(sd/8))
//     -> correction term is O(1e-5); a 2-op bit-trick rsqrt (3.5% err) gives
//        total rel err ~1e-6. Zero MUFU for contrast.

#define EPSF 1e-6f
#define EXPN 0.60653065971263342f   /* e^-0.5 */
#define EPSC (EPSF * EXPN)
#define SR 34
#define SC 68                        /* 66 real cols, padded for alignment */

__device__ __forceinline__ float4 feat(float S1, float S2, float SL,
    float a0, float b0, float c0,
    float a1, float b1, float c1,
    float a2, float b2, float c2)
{
    const float inv9 = 1.0f / 9.0f;
    float mean = S1 * inv9;
    float sd = fmaf(-S1, mean, S2);          // sum (p-mean)^2
    sd = fmaxf(sd, 1e-12f);

    // contrast = (8/9)*(1 - 2*eps/sqrt(sd/8)); bit-trick rsqrt, no NR needed
    float v = sd * 0.125f;
    float r = __int_as_float(0x5f3759df - (__float_as_int(v) >> 1));
    float contrast = fmaxf((8.0f / 9.0f) * fmaf(-2.0f * EPSF, r, 1.0f), 0.0f);

    // homogeneity needs sum |p - mean|
    float a = fabsf(a0 - mean);
    a += fabsf(b0 - mean); a += fabsf(c0 - mean);
    a += fabsf(a1 - mean); a += fabsf(b1 - mean); a += fabsf(c1 - mean);
    a += fabsf(a2 - mean); a += fabsf(b2 - mean); a += fabsf(c2 - mean);
    float homog = __fdividef(1.0f, fmaf(a, inv9, 1.0f));

    float energy  = S2 * inv9;
    float entropy = -SL * inv9;
    return make_float4(contrast, energy, entropy, homog);
}

// Load smem row s (cols j0..j0+3) for both pixels; emit p values + row sums.
#define LOADROW(s, PA, PB, PC, PD, RSL, RSR, RQL, RQR, RLL, RLR)            \
    {                                                                        \
        const float2 u  = *(const float2*)&sp[(s) * SC + j0];                \
        const float2 w  = *(const float2*)&sp[(s) * SC + j0 + 2];            \
        PA = u.x; PB = u.y; PC = w.x; PD = w.y;                              \
        float t  = PB + PC;                                                  \
        RSL = PA + t;                 RSR = t + PD;                          \
        float tq = fmaf(PB, PB, PC * PC);                                    \
        RQL = fmaf(PA, PA, tq);       RQR = fmaf(PD, PD, tq);                \
        const float2 lu = *(const float2*)&sl[(s) * SC + j0];                \
        const float2 lw = *(const float2*)&sl[(s) * SC + j0 + 2];            \
        float tl = lu.y + lw.x;                                              \
        RLL = lu.x + tl;              RLR = tl + lw.y;                       \
    }

__global__ __launch_bounds__(256, 3)
void glcm_martingale_kernel(const float* __restrict__ x, float* __restrict__ out)
{
    __shared__ __align__(16) float sp[SR * SC];  // raw values (zero-padded halo)
    __shared__ __align__(16) float sl[SR * SC];  // p * log(p + eps)

    const int bc    = blockIdx.z;                // plane (b*C + c)
    const int tileX = blockIdx.x * 64;
    const int tileY = blockIdx.y * 32;
    const float* __restrict__ xin = x + (size_t)bc * 65536;

    const int tx = threadIdx.x;                  // 0..31
    const int ty = threadIdx.y;                  // 0..7 (= warp id)

    // ---- load 34x66 halo tile (warp-strided rows, lane-strided cols) ----
    for (int rr = ty; rr < SR; rr += 8) {
        int gh = tileY - 1 + rr;
        bool rok = (unsigned)gh < 256u;
        const float* __restrict__ rowp = xin + gh * 256 + tileX - 1;
        #pragma unroll
        for (int jj = 0; jj < 3; jj++) {
            int c = tx + 32 * jj;
            if (c < SC) {
                float v = 0.0f;
                int gw = tileX - 1 + c;
                if (rok && c < 66 && (unsigned)gw < 256u) v = rowp[c];
                sp[rr * SC + c] = v;
                sl[rr * SC + c] = v * __logf(v + EPSF);
            }
        }
    }
    __syncthreads();

    const int j0 = 2 * tx;        // smem col of leftmost window tap
    const int r0 = ty * 4;        // first output row (local); smem top row = r0

    float pa0, pb0, pc0, pd0, pa1, pb1, pc1, pd1, pa2, pb2, pc2, pd2;
    float rsL0, rsR0, rqL0, rqR0, rlL0, rlR0;
    float rsL1, rsR1, rqL1, rqR1, rlL1, rlR1;
    float rsL2, rsR2, rqL2, rqR2, rlL2, rlR2;

    LOADROW(r0,     pa0, pb0, pc0, pd0, rsL0, rsR0, rqL0, rqR0, rlL0, rlR0);
    LOADROW(r0 + 1, pa1, pb1, pc1, pd1, rsL1, rsR1, rqL1, rqR1, rlL1, rlR1);

    const size_t plane = 65536;
    float* obase = out + (size_t)bc * 4 * plane
                       + (size_t)(tileY + r0) * 256 + (tileX + j0);

    #pragma unroll
    for (int k = 0; k < 4; k++) {
        LOADROW(r0 + k + 2, pa2, pb2, pc2, pd2, rsL2, rsR2, rqL2, rqR2, rlL2, rlR2);

        float S1L = rsL0 + rsL1 + rsL2;
        float S2L = rqL0 + rqL1 + rqL2;
        float SLL = rlL0 + rlL1 + rlL2;
        float S1R = rsR0 + rsR1 + rsR2;
        float S2R = rqR0 + rqR1 + rqR2;
        float SLR = rlR0 + rlR1 + rlR2;

        float4 fL = feat(S1L, S2L, SLL, pa0, pb0, pc0, pa1, pb1, pc1, pa2, pb2, pc2);
        float4 fR = feat(S1R, S2R, SLR, pb0, pc0, pd0, pb1, pc1, pd1, pb2, pc2, pd2);

        float* o = obase + (size_t)k * 256;
        *(float2*)&o[0]         = make_float2(fmaf(fL.x, EXPN, EPSC), fmaf(fR.x, EXPN, EPSC));
        *(float2*)&o[plane]     = make_float2(fmaf(fL.y, EXPN, EPSC), fmaf(fR.y, EXPN, EPSC));
        *(float2*)&o[2 * plane] = make_float2(fmaf(fL.z, EXPN, EPSC), fmaf(fR.z, EXPN, EPSC));
        *(float2*)&o[3 * plane] = make_float2(fmaf(fL.w, EXPN, EPSC), fmaf(fR.w, EXPN, EPSC));

        // roll window down one row
        pa0 = pa1; pb0 = pb1; pc0 = pc1; pd0 = pd1;
        pa1 = pa2; pb1 = pb2; pc1 = pc2; pd1 = pd2;
        rsL0 = rsL1; rsR0 = rsR1; rqL0 = rqL1; rqR0 = rqR1; rlL0 = rlL1; rlR0 = rlR1;
        rsL1 = rsL2; rsR1 = rsR2; rqL1 = rqL2; rqR1 = rqR2; rlL1 = rlL2; rlR1 = rlR2;
    }
}

extern "C" void kernel_launch(void* const* d_in, const int* in_sizes, int n_in,
                              void* d_out, int out_size)
{
    const float* x = (const float*)d_in[0];
    float* out     = (float*)d_out;

    dim3 block(32, 8, 1);                 // 256 threads, 8 warps
    dim3 grid(256 / 64, 256 / 32, 128);   // 4 x 8 x 128 = 4096 blocks
    glcm_martingale_kernel<<<grid, block>>>(x, out);
}